// round 6
// baseline (speedup 1.0000x reference)
#include <cuda_runtime.h>
#include <cuda_fp16.h>
#include <cstdint>

// ---------------------------------------------------------------------------
#define TT   64
#define BB   32
#define NTB  2048
#define HID  256
#define FEAT 1152

__device__ __half g_a1[2048u*32*42*42];   // NHWC f16
__device__ __half g_a2[2048u*32*21*21];   // NHWC f16
__device__ __half g_xf[2048u*1152];       // f16, reference feature order
__device__ __half g_wih[768u*1152];       // W_ih pre-converted to f16
__device__ float  g_gi[2048u*768];
__device__ float  g_outs[2048u*256];
__device__ float  g_h[2][BB*HID];
__device__ unsigned g_flags2[64];         // monotonic barrier flags (zero-init)

// ---------------------------------------------------------------------------
__device__ __forceinline__ void mma16(float4& d, uint32_t a0, uint32_t a1,
                                      uint32_t a2, uint32_t a3,
                                      uint32_t b0, uint32_t b1) {
    asm volatile("mma.sync.aligned.m16n8k16.row.col.f32.f16.f16.f32 "
        "{%0,%1,%2,%3},{%4,%5,%6,%7},{%8,%9},{%0,%1,%2,%3};"
        : "+f"(d.x), "+f"(d.y), "+f"(d.z), "+f"(d.w)
        : "r"(a0), "r"(a1), "r"(a2), "r"(a3), "r"(b0), "r"(b1));
}
__device__ __forceinline__ float eluf(float x) { return x > 0.f ? x : expm1f(x); }

__device__ __forceinline__ void cp16(void* smem, const void* g) {
    uint32_t s = (uint32_t)__cvta_generic_to_shared(smem);
    asm volatile("cp.async.ca.shared.global [%0], [%1], 16;" :: "r"(s), "l"(g));
}
__device__ __forceinline__ unsigned ld_rel(const unsigned* p) {
    unsigned v; asm volatile("ld.global.relaxed.gpu.u32 %0, [%1];" : "=r"(v) : "l"(p));
    return v;
}
__device__ __forceinline__ void st_rel(unsigned* p, unsigned v) {
    asm volatile("st.global.relaxed.gpu.u32 [%0], %1;" :: "l"(p), "r"(v));
}

// ---------------------------------------------------------------------------
// fp16 implicit-GEMM conv3x3 stride2 pad1, OC=32, m16n8k16 (layers 1 & 2).
// ---------------------------------------------------------------------------
template<int IC, int IH, int OH, int BAND, int INMODE>
__global__ void __launch_bounds__(256) conv_f16(const void* __restrict__ in_,
        const float* __restrict__ wgt, const float* __restrict__ bias,
        void* __restrict__ out_)
{
    constexpr int OW = OH, IW = IH;
    constexpr bool C1 = (IC == 4);
    constexpr int XS = C1 ? 4 : 40;
    constexpr int RW = (IW+2)*XS;
    constexpr int ROWS = 2*BAND + 1;
    constexpr int SIN = ROWS*RW;
    constexpr int KS = C1 ? 3 : 18;
    constexpr int APAD = C1 ? 56 : 296;
    constexpr int NPIX = BAND*OW;
    constexpr int NT8 = (NPIX+7)/8;
    constexpr int NTW = (NT8+3)/4;
    constexpr int OHW = OH*OW;

    extern __shared__ __half sh[];
    __half* s_in = sh;
    __half* s_w  = sh + SIN;

    const int tid = threadIdx.x;
    const int n0 = blockIdx.x;
    const int oy0 = blockIdx.y * BAND;
    const int ybase = 2*oy0 - 1;

    for (int i = tid; i < SIN/8; i += 256) ((uint4*)s_in)[i] = make_uint4(0,0,0,0);

    if (C1) {
        for (int i = tid; i < 32*48; i += 256) {
            int oc = i/48, r = i - oc*48;
            int ky = r>>4, rr = r&15, kx = rr>>2, ic = rr&3;
            float v = (kx < 3) ? wgt[((oc*4+ic)*3+ky)*3+kx] : 0.f;
            s_w[oc*APAD + r] = __float2half_rn(v);
        }
    } else {
        for (int i = tid; i < 32*288; i += 256) {
            int oc = i/288, r = i - oc*288;
            int s = r>>4, c = r&15;
            int tap = s>>1, ch = s&1;
            int ky = tap/3, kx = tap - ky*3;
            s_w[oc*APAD + r] = __float2half_rn(wgt[((oc*32 + ch*16 + c)*3+ky)*3+kx]);
        }
    }

    const int y_lo = (ybase < 0) ? 0 : ybase;
    int y_hi = ybase + ROWS - 1; if (y_hi > IH-1) y_hi = IH-1;
    const int nrows = y_hi - y_lo + 1;

    if (INMODE == 0) {
        const float* inF = (const float*)in_;
        for (int i = tid; i < nrows*IW; i += 256) {
            int x = i % IW; int yy = i / IW; int y = y_lo + yy;
            const float* p = inF + (((size_t)n0*4)*IH + y)*IW + x;
            __half2 h01 = __floats2half2_rn(p[0], p[(size_t)IH*IW]);
            __half2 h23 = __floats2half2_rn(p[2*(size_t)IH*IW], p[3*(size_t)IH*IW]);
            __half* d = s_in + (y - ybase)*RW + (x+1)*4;
            *(__half2*)d = h01; *(__half2*)(d+2) = h23;
        }
    } else {
        const __half* inH = (const __half*)in_;
        for (int i = tid; i < nrows*IW*4; i += 256) {
            int g = i & 3, q = i >> 2;
            int x = q % IW; int yy = q / IW;
            int y = y_lo + yy;
            uint4 v = *(const uint4*)(inH + (((size_t)n0*IH + y)*IW + x)*32 + g*8);
            *(uint4*)(s_in + (y - ybase)*RW + (x+1)*40 + g*8) = v;
        }
    }
    __syncthreads();

    const int lane = tid & 31, warp = tid >> 5;
    const int m0 = (warp & 1)*16;
    const int ng = warp >> 1;
    const int gq = lane >> 2, tq = lane & 3;

    int pixbase[NTW];
    #pragma unroll
    for (int j = 0; j < NTW; j++) {
        int tile = ng + 4*j;
        int p = tile*8 + gq;
        int pp = (p < NPIX) ? p : 0;
        int dy = pp / OW, ox = pp - dy*OW;
        pixbase[j] = 2*dy*RW + 2*ox*XS + 2*tq;
    }

    float4 acc[NTW];
    #pragma unroll
    for (int j = 0; j < NTW; j++) acc[j] = make_float4(0.f,0.f,0.f,0.f);

    const __half* swr = s_w + (m0 + gq)*APAD + 2*tq;
    #pragma unroll
    for (int s = 0; s < KS; s++) {
        uint32_t a0 = *(const uint32_t*)(swr + s*16);
        uint32_t a1 = *(const uint32_t*)(swr + s*16 + 8*APAD);
        uint32_t a2 = *(const uint32_t*)(swr + s*16 + 8);
        uint32_t a3 = *(const uint32_t*)(swr + s*16 + 8*APAD + 8);
        int off;
        if (C1) { off = s*RW; }
        else { int tap = s>>1, ch = s&1; int ky = tap/3, kx = tap - ky*3;
               off = ky*RW + kx*40 + ch*16; }
        #pragma unroll
        for (int j = 0; j < NTW; j++) {
            const __half* bp = s_in + pixbase[j] + off;
            mma16(acc[j], a0, a1, a2, a3,
                  *(const uint32_t*)bp, *(const uint32_t*)(bp + 8));
        }
    }

    const int oc = m0 + gq;
    const float b0v = __ldg(&bias[oc]);
    const float b8v = __ldg(&bias[oc+8]);
    __half* ob0 = (__half*)out_ + ((size_t)n0*OHW + oy0*OW)*32;

    #pragma unroll
    for (int j = 0; j < NTW; j++) {
        int tile = ng + 4*j;
        if (tile >= NT8) continue;
        int pc = tile*8 + tq*2;
        if (pc < NPIX) {
            ob0[pc*32 + oc]   = __float2half_rn(eluf(acc[j].x + b0v));
            ob0[pc*32 + oc+8] = __float2half_rn(eluf(acc[j].z + b8v));
        }
        if (pc+1 < NPIX) {
            ob0[(pc+1)*32 + oc]   = __float2half_rn(eluf(acc[j].y + b0v));
            ob0[(pc+1)*32 + oc+8] = __float2half_rn(eluf(acc[j].w + b8v));
        }
    }
}

// ---------------------------------------------------------------------------
// Fused conv3 + conv4 (unchanged from R5)
// ---------------------------------------------------------------------------
#define RW3  920
#define SIN3 (23*920)
#define RW4  520
#define SIN4 (13*520)
#define C34_SMEM ((SIN3 + SIN4 + 2*32*296) * 2)

__global__ void __launch_bounds__(256) conv34_f16(const __half* __restrict__ a2,
        const float* __restrict__ w3, const float* __restrict__ b3f,
        const float* __restrict__ w4, const float* __restrict__ b4f,
        __half* __restrict__ xf)
{
    extern __shared__ __half sh[];
    __half* s_in = sh;
    __half* s_c4 = sh + SIN3;
    __half* s_w3 = sh + SIN3 + SIN4;
    __half* s_w4 = s_w3 + 32*296;

    const int tid = threadIdx.x;
    const int n = blockIdx.x;

    for (int i = tid; i < (SIN3+SIN4)/8; i += 256) ((uint4*)s_in)[i] = make_uint4(0,0,0,0);

    for (int i = tid; i < 32*288; i += 256) {
        int oc = i/288, r = i - oc*288;
        int s = r>>4, c = r&15;
        int tap = s>>1, ch = s&1;
        int ky = tap/3, kx = tap - ky*3;
        int widx = ((oc*32 + ch*16 + c)*3+ky)*3+kx;
        s_w3[oc*296 + r] = __float2half_rn(w3[widx]);
        s_w4[oc*296 + r] = __float2half_rn(w4[widx]);
    }

    for (int i = tid; i < 21*21*4; i += 256) {
        int g = i & 3, q = i >> 2;
        int x = q % 21; int y = q / 21;
        uint4 v = *(const uint4*)(a2 + (((size_t)n*21 + y)*21 + x)*32 + g*8);
        *(uint4*)(s_in + (y+1)*RW3 + (x+1)*40 + g*8) = v;
    }
    __syncthreads();

    const int lane = tid & 31, warp = tid >> 5;
    const int m0 = (warp & 1)*16;
    const int ng = warp >> 1;
    const int gq = lane >> 2, tq = lane & 3;
    const int oc = m0 + gq;

    {
        int pixbase[4];
        #pragma unroll
        for (int j = 0; j < 4; j++) {
            int p = (ng + 4*j)*8 + gq;
            int pp = (p < 121) ? p : 0;
            int dy = pp / 11, ox = pp - dy*11;
            pixbase[j] = 2*dy*RW3 + 2*ox*40 + 2*tq;
        }
        float4 acc[4];
        #pragma unroll
        for (int j = 0; j < 4; j++) acc[j] = make_float4(0.f,0.f,0.f,0.f);

        const __half* swr = s_w3 + oc*296 + 2*tq;
        #pragma unroll
        for (int s = 0; s < 18; s++) {
            uint32_t a0 = *(const uint32_t*)(swr + s*16);
            uint32_t a1 = *(const uint32_t*)(swr + s*16 + 8*296);
            uint32_t a2r = *(const uint32_t*)(swr + s*16 + 8);
            uint32_t a3r = *(const uint32_t*)(swr + s*16 + 8*296 + 8);
            int tap = s>>1, ch = s&1; int ky = tap/3, kx = tap - ky*3;
            int off = ky*RW3 + kx*40 + ch*16;
            #pragma unroll
            for (int j = 0; j < 4; j++) {
                const __half* bp = s_in + pixbase[j] + off;
                mma16(acc[j], a0, a1, a2r, a3r,
                      *(const uint32_t*)bp, *(const uint32_t*)(bp + 8));
            }
        }
        const float b0v = __ldg(&b3f[oc]);
        const float b8v = __ldg(&b3f[oc+8]);
        #pragma unroll
        for (int j = 0; j < 4; j++) {
            int pc = (ng + 4*j)*8 + tq*2;
            #pragma unroll
            for (int u = 0; u < 2; u++) {
                int p = pc + u;
                if (p < 121) {
                    int y = p / 11, x = p - y*11;
                    __half* d = s_c4 + (y+1)*RW4 + (x+1)*40;
                    float v0 = (u == 0) ? acc[j].x : acc[j].y;
                    float v8 = (u == 0) ? acc[j].z : acc[j].w;
                    d[oc]   = __float2half_rn(eluf(v0 + b0v));
                    d[oc+8] = __float2half_rn(eluf(v8 + b8v));
                }
            }
        }
    }
    __syncthreads();

    {
        int pixbase[2];
        #pragma unroll
        for (int j = 0; j < 2; j++) {
            int tile = ng + 4*j;
            int p = tile*8 + gq;
            int pp = (p < 36) ? p : 0;
            int dy = pp / 6, ox = pp - dy*6;
            pixbase[j] = 2*dy*RW4 + 2*ox*40 + 2*tq;
        }
        float4 acc[2];
        acc[0] = make_float4(0.f,0.f,0.f,0.f); acc[1] = acc[0];

        const __half* swr = s_w4 + oc*296 + 2*tq;
        #pragma unroll
        for (int s = 0; s < 18; s++) {
            uint32_t a0 = *(const uint32_t*)(swr + s*16);
            uint32_t a1 = *(const uint32_t*)(swr + s*16 + 8*296);
            uint32_t a2r = *(const uint32_t*)(swr + s*16 + 8);
            uint32_t a3r = *(const uint32_t*)(swr + s*16 + 8*296 + 8);
            int tap = s>>1, ch = s&1; int ky = tap/3, kx = tap - ky*3;
            int off = ky*RW4 + kx*40 + ch*16;
            #pragma unroll
            for (int j = 0; j < 2; j++) {
                const __half* bp = s_c4 + pixbase[j] + off;
                mma16(acc[j], a0, a1, a2r, a3r,
                      *(const uint32_t*)bp, *(const uint32_t*)(bp + 8));
            }
        }
        const float b0v = __ldg(&b4f[oc]);
        const float b8v = __ldg(&b4f[oc+8]);
        __half* ob = xf + (size_t)n*1152;
        #pragma unroll
        for (int j = 0; j < 2; j++) {
            int tile = ng + 4*j;
            if (tile >= 5) continue;
            int pc = tile*8 + tq*2;
            if (pc < 36) {
                ob[oc*36 + pc]     = __float2half_rn(eluf(acc[j].x + b0v));
                ob[(oc+8)*36 + pc] = __float2half_rn(eluf(acc[j].z + b8v));
            }
            if (pc+1 < 36) {
                ob[oc*36 + pc+1]     = __float2half_rn(eluf(acc[j].y + b0v));
                ob[(oc+8)*36 + pc+1] = __float2half_rn(eluf(acc[j].w + b8v));
            }
        }
    }
}

// ---------------------------------------------------------------------------
// W_ih f32 -> f16 one-time conversion
// ---------------------------------------------------------------------------
__global__ void __launch_bounds__(256) wcvt(const float* __restrict__ W, __half* __restrict__ O) {
    int i = blockIdx.x * 256 + threadIdx.x;           // float4 index
    #pragma unroll
    for (int r = 0; r < 2; r++) {
        int idx = i + r * 110592;
        float4 v = *(const float4*)(W + idx*4);
        __half2 p0 = __floats2half2_rn(v.x, v.y);
        __half2 p1 = __floats2half2_rn(v.z, v.w);
        uint2 o; o.x = *(uint32_t*)&p0; o.y = *(uint32_t*)&p1;
        *(uint2*)(O + idx*4) = o;
    }
}

// ---------------------------------------------------------------------------
// gi[2048,768] = xf(f16) @ Wih(f16)^T + b_ih, cp.async double-buffered.
// 64x64 tile, BK=32, 8 warps = 2m x 4n, warp tile 32x16.
// ---------------------------------------------------------------------------
__global__ void __launch_bounds__(256) gemm_f16(const __half* __restrict__ A,
        const __half* __restrict__ B, const float* __restrict__ bias,
        float* __restrict__ C)
{
    constexpr int ST = 48;
    __shared__ __half As[2][64*ST], Bs[2][64*ST];
    const int bm = blockIdx.y*64, bn = blockIdx.x*64;
    const int tid = threadIdx.x, lane = tid&31, warp = tid>>5;
    const int wm = (warp&1)*32, wn = (warp>>1)*16;
    const int gq = lane>>2, tq = lane&3;
    const int ldr = tid>>2, ldc = (tid&3)*8;

    const __half* Ag = A + (size_t)(bm+ldr)*FEAT + ldc;
    const __half* Bg = B + (size_t)(bn+ldr)*FEAT + ldc;
    __half* Ad = &As[0][ldr*ST + ldc];
    __half* Bd = &Bs[0][ldr*ST + ldc];

    float4 acc[2][2];
    #pragma unroll
    for (int i = 0; i < 2; i++)
        #pragma unroll
        for (int j = 0; j < 2; j++) acc[i][j] = make_float4(0.f,0.f,0.f,0.f);

    cp16(Ad, Ag); cp16(Bd, Bg);
    asm volatile("cp.async.commit_group;");

    #pragma unroll 1
    for (int i = 0; i < 36; i++) {
        if (i + 1 < 36) {
            int st = (i+1)&1;
            cp16(Ad + st*64*ST - (i&1)*0 + (st ? 64*ST : -64*ST)*0 , Ag); // placeholder (not used)
        }
        break;
    }
    // (rewritten loop below — keep single canonical version)
    #pragma unroll 1
    for (int i = 0; i < 36; i++) {
        if (i + 1 < 36) {
            int st = (i+1)&1;
            cp16(&As[st][ldr*ST + ldc], Ag + (i+1)*32);
            cp16(&Bs[st][ldr*ST + ldc], Bg + (i+1)*32);
            asm volatile("cp.async.commit_group;");
            asm volatile("cp.async.wait_group 1;");
        } else {
            asm volatile("cp.async.wait_group 0;");
        }
        __syncthreads();
        const int cs = i&1;
        #pragma unroll
        for (int s = 0; s < 2; s++) {
            #pragma unroll
            for (int mi = 0; mi < 2; mi++) {
                const __half* ap = &As[cs][(wm + mi*16 + gq)*ST + s*16 + 2*tq];
                uint32_t a0 = *(const uint32_t*)ap;
                uint32_t a1 = *(const uint32_t*)(ap + 8*ST);
                uint32_t a2 = *(const uint32_t*)(ap + 8);
                uint32_t a3 = *(const uint32_t*)(ap + 8*ST + 8);
                #pragma unroll
                for (int ni = 0; ni < 2; ni++) {
                    const __half* bp = &Bs[cs][(wn + ni*8 + gq)*ST + s*16 + 2*tq];
                    mma16(acc[mi][ni], a0, a1, a2, a3,
                          *(const uint32_t*)bp, *(const uint32_t*)(bp + 8));
                }
            }
        }
        __syncthreads();
    }
    #pragma unroll
    for (int mi = 0; mi < 2; mi++) {
        #pragma unroll
        for (int ni = 0; ni < 2; ni++) {
            int row = bm + wm + mi*16 + gq;
            int col = bn + wn + ni*8 + tq*2;
            float bb0 = __ldg(&bias[col]), bb1 = __ldg(&bias[col+1]);
            C[(size_t)row*768 + col]       = acc[mi][ni].x + bb0;
            C[(size_t)row*768 + col + 1]   = acc[mi][ni].y + bb1;
            C[(size_t)(row+8)*768 + col]   = acc[mi][ni].z + bb0;
            C[(size_t)(row+8)*768 + col+1] = acc[mi][ni].w + bb1;
        }
    }
}

// ---------------------------------------------------------------------------
// Persistent GRU v3: 64 blocks x 256 threads, k-split x2.
// s_h XOR-swizzled (conflict-free float4 loads across b); flag-array barrier
// (no atomics, no nanosleep); gi prefetched at step start.
// ---------------------------------------------------------------------------
#define GRU_BLOCKS 64
#define GRU_THREADS 256

__device__ __forceinline__ void gbar(int bx, int tid, unsigned target) {
    __threadfence();
    __syncthreads();
    if (tid == 0) st_rel(&g_flags2[bx], target);
    if (tid < GRU_BLOCKS) {
        while ((int)(ld_rel(&g_flags2[tid]) - target) < 0) {}
    }
    __threadfence();
    __syncthreads();
}

__global__ void gru_kernel(const float* __restrict__ rnn_in, const float* __restrict__ mask,
                           const float* __restrict__ W_hh, const float* __restrict__ b_hh,
                           const float* __restrict__ gi_all, float* __restrict__ outs,
                           float* __restrict__ hfin) {
    __shared__ float s_w[12*256];
    __shared__ float s_h[32*256];
    __shared__ float s_p[3*256];

    const int tid = threadIdx.x;
    const int bx  = blockIdx.x;
    const unsigned base = ld_rel(&g_flags2[bx]);   // only this block writes its flag

    for (int i = tid; i < 12*64; i += GRU_THREADS) {
        int rl = i >> 6, kq = i & 63;
        int gate = rl >> 2, gj2 = rl & 3;
        float4 w = *(const float4*)&W_hh[(size_t)(gate*256 + bx*4 + gj2)*256 + kq*4];
        *(float4*)&s_w[rl*256 + kq*4] = w;
    }
    if (bx == 0) {
        for (int i = tid; i < BB*HID; i += GRU_THREADS) g_h[0][i] = rnn_in[i];
    }
    gbar(bx, tid, base + 1);

    const int half = tid >> 7;
    const int r    = tid & 127;
    const int gj = r >> 5, b = r & 31;
    const int g = bx*4 + gj;
    const int c = b & 7;
    const float br = __ldg(&b_hh[g]);
    const float bz = __ldg(&b_hh[256 + g]);
    const float bn = __ldg(&b_hh[512 + g]);

    float4* s_h4 = (float4*)s_h;
    const float4* s_w4 = (const float4*)s_w;

    for (int t = 0; t < TT; t++) {
        // prefetch gi for this step (tid<128 consumes)
        float gir = 0.f, giz = 0.f, gin = 0.f;
        if (tid < 128) {
            const float* gi = gi_all + (size_t)(t*32 + b)*768;
            gir = __ldg(&gi[g]); giz = __ldg(&gi[256 + g]); gin = __ldg(&gi[512 + g]);
        }
        const float* hprev = g_h[t & 1];
        for (int i = tid; i < 32*64; i += GRU_THREADS) {
            int bb = i >> 6, kq = i & 63;
            float m = __ldg(&mask[t*32 + bb]);
            float4 hv = __ldcg((const float4*)&hprev[bb*256 + kq*4]);
            hv.x *= m; hv.y *= m; hv.z *= m; hv.w *= m;
            s_h4[bb*64 + (kq ^ (bb & 7))] = hv;   // XOR swizzle -> conflict-free reads
        }
        __syncthreads();

        float4 ar = make_float4(0.f,0.f,0.f,0.f), az = ar, an = ar;
        const float4* hrow = s_h4 + b*64;
        const float4* wr4 = s_w4 + (0 + gj)*64;
        const float4* wz4 = s_w4 + (4 + gj)*64;
        const float4* wn4 = s_w4 + (8 + gj)*64;
        #pragma unroll 8
        for (int kq = 0; kq < 32; kq++) {
            int kqg = half*32 + kq;
            float4 h = hrow[kqg ^ c];
            float4 wr = wr4[kqg], wz = wz4[kqg], wn = wn4[kqg];
            ar.x += h.x*wr.x; ar.y += h.y*wr.y; ar.z += h.z*wr.z; ar.w += h.w*wr.w;
            az.x += h.x*wz.x; az.y += h.y*wz.y; az.z += h.z*wz.z; az.w += h.w*wz.w;
            an.x += h.x*wn.x; an.y += h.y*wn.y; an.z += h.z*wn.z; an.w += h.w*wn.w;
        }
        s_p[0*256 + tid] = ar.x + ar.y + ar.z + ar.w;
        s_p[1*256 + tid] = az.x + az.y + az.z + az.w;
        s_p[2*256 + tid] = an.x + an.y + an.z + an.w;
        __syncthreads();
        if (tid < 128) {
            float ghr = s_p[0*256 + tid] + s_p[0*256 + tid + 128] + br;
            float ghz = s_p[1*256 + tid] + s_p[1*256 + tid + 128] + bz;
            float ghn = s_p[2*256 + tid] + s_p[2*256 + tid + 128] + bn;
            float rr = 1.f / (1.f + expf(-(gir + ghr)));
            float zz = 1.f / (1.f + expf(-(giz + ghz)));
            float nn = tanhf(gin + rr*ghn);
            float hold = s_h[b*256 + (((g>>2) ^ c)<<2) + (g&3)];
            float hn = (1.f - zz)*nn + zz*hold;
            g_h[(t + 1) & 1][b*256 + g] = hn;
            outs[(size_t)(t*32 + b)*256 + g] = hn;
            if (t == TT - 1) hfin[b*256 + g] = hn;
        }
        gbar(bx, tid, base + 2 + t);
    }
}

// ---------------------------------------------------------------------------
// Heads
// ---------------------------------------------------------------------------
__global__ void heads_kernel(const float* __restrict__ outs, const int* __restrict__ actions,
                             const float* __restrict__ Wc, const float* __restrict__ bc,
                             const float* __restrict__ Wa, const float* __restrict__ ba,
                             float* __restrict__ d_out) {
    int warp = (blockIdx.x * blockDim.x + threadIdx.x) >> 5;
    int lane = threadIdx.x & 31;
    if (warp >= NTB) return;
    const float* o = outs + (size_t)warp * 256;

    float acc[13];
    #pragma unroll
    for (int g = 0; g < 13; g++) acc[g] = 0.f;
    #pragma unroll
    for (int i = 0; i < 8; i++) {
        int k = lane + 32*i;
        float x = o[k];
        acc[0] += x * __ldg(&Wc[k]);
        #pragma unroll
        for (int g = 0; g < 12; g++) acc[1 + g] += x * __ldg(&Wa[g*256 + k]);
    }
    #pragma unroll
    for (int g = 0; g < 13; g++) {
        #pragma unroll
        for (int s = 16; s > 0; s >>= 1) acc[g] += __shfl_xor_sync(0xFFFFFFFFu, acc[g], s);
    }
    if (lane == 0) {
        float v = acc[0] + bc[0];
        float l[12];
        float m = -1e30f;
        #pragma unroll
        for (int g = 0; g < 12; g++) { l[g] = acc[1 + g] + ba[g]; m = fmaxf(m, l[g]); }
        float s = 0.f, sl = 0.f;
        #pragma unroll
        for (int g = 0; g < 12; g++) {
            float e = expf(l[g] - m);
            s += e; sl += e * l[g];
        }
        float logZ = m + logf(s);
        int a = actions[warp];
        d_out[warp]        = v;
        d_out[2048 + warp] = (float)a;
        d_out[4096 + warp] = l[a] - logZ;
        d_out[6144 + warp] = logZ - sl / s;
    }
}

// ---------------------------------------------------------------------------
// Host launcher
// ---------------------------------------------------------------------------
#define C1_SMEM ((13*344      + 32*56 ) * 2)
#define C2_SMEM ((15*(44*40)  + 32*296) * 2)

extern "C" void kernel_launch(void* const* d_in, const int* in_sizes, int n_in,
                              void* d_out, int out_size) {
    const float* inputs = (const float*)d_in[0];
    const float* rnn_in = (const float*)d_in[1];
    const float* mask   = (const float*)d_in[2];
    const int*   actions= (const int*)  d_in[3];
    const float* w1 = (const float*)d_in[4];  const float* b1 = (const float*)d_in[5];
    const float* w2 = (const float*)d_in[6];  const float* b2 = (const float*)d_in[7];
    const float* w3 = (const float*)d_in[8];  const float* b3 = (const float*)d_in[9];
    const float* w4 = (const float*)d_in[10]; const float* b4 = (const float*)d_in[11];
    const float* W_ih = (const float*)d_in[12];
    const float* W_hh = (const float*)d_in[13];
    const float* b_ih = (const float*)d_in[14];
    const float* b_hh = (const float*)d_in[15];
    const float* Wc = (const float*)d_in[16]; const float* bc = (const float*)d_in[17];
    const float* Wa = (const float*)d_in[18]; const float* ba = (const float*)d_in[19];
    float* out = (float*)d_out;

    __half *a1, *a2, *xf, *wih;
    float *gi, *outs;
    cudaGetSymbolAddress((void**)&a1, g_a1);
    cudaGetSymbolAddress((void**)&a2, g_a2);
    cudaGetSymbolAddress((void**)&xf, g_xf);
    cudaGetSymbolAddress((void**)&wih, g_wih);
    cudaGetSymbolAddress((void**)&gi, g_gi);
    cudaGetSymbolAddress((void**)&outs, g_outs);

    cudaFuncSetAttribute((conv_f16<4,84,42,6,0>),  cudaFuncAttributeMaxDynamicSharedMemorySize, C1_SMEM);
    cudaFuncSetAttribute((conv_f16<32,42,21,7,1>), cudaFuncAttributeMaxDynamicSharedMemorySize, C2_SMEM);
    cudaFuncSetAttribute(conv34_f16,               cudaFuncAttributeMaxDynamicSharedMemorySize, C34_SMEM);

    wcvt<<<432, 256>>>(W_ih, wih);
    conv_f16<4,84,42,6,0>  <<<dim3(NTB,7), 256, C1_SMEM>>>(inputs, w1, b1, a1);
    conv_f16<32,42,21,7,1> <<<dim3(NTB,3), 256, C2_SMEM>>>(a1, w2, b2, a2);
    conv34_f16             <<<NTB, 256, C34_SMEM>>>(a2, w3, b3, w4, b4, xf);

    gemm_f16<<<dim3(768/64, 2048/64), 256>>>(xf, wih, b_ih, gi);

    gru_kernel<<<GRU_BLOCKS, GRU_THREADS>>>(rnn_in, mask, W_hh, b_hh, gi, outs, out + 8192);

    heads_kernel<<<256, 256>>>(outs, actions, Wc, bc, Wa, ba, out);
}

// round 7
// speedup vs baseline: 1.2143x; 1.2143x over previous
#include <cuda_runtime.h>
#include <cuda_fp16.h>
#include <cstdint>

// ---------------------------------------------------------------------------
#define TT   64
#define BB   32
#define NTB  2048
#define HID  256
#define FEAT 1152

__device__ __half g_a1[2048u*32*42*42];   // NHWC f16
__device__ __half g_a2[2048u*32*21*21];   // NHWC f16
__device__ __half g_xf[2048u*1152];       // f16, reference feature order
__device__ __half g_wih[768u*1152];       // W_ih pre-converted to f16
__device__ float  g_gi[2048u*768];
__device__ float  g_outs[2048u*256];
__device__ float  g_h[2][BB*HID];
__device__ unsigned g_bar_cnt = 0;
__device__ unsigned g_bar_phase = 0;

// ---------------------------------------------------------------------------
__device__ __forceinline__ void mma16(float4& d, uint32_t a0, uint32_t a1,
                                      uint32_t a2, uint32_t a3,
                                      uint32_t b0, uint32_t b1) {
    asm volatile("mma.sync.aligned.m16n8k16.row.col.f32.f16.f16.f32 "
        "{%0,%1,%2,%3},{%4,%5,%6,%7},{%8,%9},{%0,%1,%2,%3};"
        : "+f"(d.x), "+f"(d.y), "+f"(d.z), "+f"(d.w)
        : "r"(a0), "r"(a1), "r"(a2), "r"(a3), "r"(b0), "r"(b1));
}
__device__ __forceinline__ float eluf(float x) { return x > 0.f ? x : expm1f(x); }

__device__ __forceinline__ void cp16(void* smem, const void* g) {
    uint32_t s = (uint32_t)__cvta_generic_to_shared(smem);
    asm volatile("cp.async.ca.shared.global [%0], [%1], 16;" :: "r"(s), "l"(g));
}

// ---------------------------------------------------------------------------
// fp16 implicit-GEMM conv3x3 stride2 pad1, OC=32, m16n8k16 (layers 1 & 2).
// ---------------------------------------------------------------------------
template<int IC, int IH, int OH, int BAND, int INMODE>
__global__ void __launch_bounds__(256) conv_f16(const void* __restrict__ in_,
        const float* __restrict__ wgt, const float* __restrict__ bias,
        void* __restrict__ out_)
{
    constexpr int OW = OH, IW = IH;
    constexpr bool C1 = (IC == 4);
    constexpr int XS = C1 ? 4 : 40;
    constexpr int RW = (IW+2)*XS;
    constexpr int ROWS = 2*BAND + 1;
    constexpr int SIN = ROWS*RW;
    constexpr int KS = C1 ? 3 : 18;
    constexpr int APAD = C1 ? 56 : 296;
    constexpr int NPIX = BAND*OW;
    constexpr int NT8 = (NPIX+7)/8;
    constexpr int NTW = (NT8+3)/4;
    constexpr int OHW = OH*OW;

    extern __shared__ __half sh[];
    __half* s_in = sh;
    __half* s_w  = sh + SIN;

    const int tid = threadIdx.x;
    const int n0 = blockIdx.x;
    const int oy0 = blockIdx.y * BAND;
    const int ybase = 2*oy0 - 1;

    for (int i = tid; i < SIN/8; i += 256) ((uint4*)s_in)[i] = make_uint4(0,0,0,0);

    if (C1) {
        for (int i = tid; i < 32*48; i += 256) {
            int oc = i/48, r = i - oc*48;
            int ky = r>>4, rr = r&15, kx = rr>>2, ic = rr&3;
            float v = (kx < 3) ? wgt[((oc*4+ic)*3+ky)*3+kx] : 0.f;
            s_w[oc*APAD + r] = __float2half_rn(v);
        }
    } else {
        for (int i = tid; i < 32*288; i += 256) {
            int oc = i/288, r = i - oc*288;
            int s = r>>4, c = r&15;
            int tap = s>>1, ch = s&1;
            int ky = tap/3, kx = tap - ky*3;
            s_w[oc*APAD + r] = __float2half_rn(wgt[((oc*32 + ch*16 + c)*3+ky)*3+kx]);
        }
    }

    const int y_lo = (ybase < 0) ? 0 : ybase;
    int y_hi = ybase + ROWS - 1; if (y_hi > IH-1) y_hi = IH-1;
    const int nrows = y_hi - y_lo + 1;

    if (INMODE == 0) {
        const float* inF = (const float*)in_;
        for (int i = tid; i < nrows*IW; i += 256) {
            int x = i % IW; int yy = i / IW; int y = y_lo + yy;
            const float* p = inF + (((size_t)n0*4)*IH + y)*IW + x;
            __half2 h01 = __floats2half2_rn(p[0], p[(size_t)IH*IW]);
            __half2 h23 = __floats2half2_rn(p[2*(size_t)IH*IW], p[3*(size_t)IH*IW]);
            __half* d = s_in + (y - ybase)*RW + (x+1)*4;
            *(__half2*)d = h01; *(__half2*)(d+2) = h23;
        }
    } else {
        const __half* inH = (const __half*)in_;
        for (int i = tid; i < nrows*IW*4; i += 256) {
            int g = i & 3, q = i >> 2;
            int x = q % IW; int yy = q / IW;
            int y = y_lo + yy;
            uint4 v = *(const uint4*)(inH + (((size_t)n0*IH + y)*IW + x)*32 + g*8);
            *(uint4*)(s_in + (y - ybase)*RW + (x+1)*40 + g*8) = v;
        }
    }
    __syncthreads();

    const int lane = tid & 31, warp = tid >> 5;
    const int m0 = (warp & 1)*16;
    const int ng = warp >> 1;
    const int gq = lane >> 2, tq = lane & 3;

    int pixbase[NTW];
    #pragma unroll
    for (int j = 0; j < NTW; j++) {
        int tile = ng + 4*j;
        int p = tile*8 + gq;
        int pp = (p < NPIX) ? p : 0;
        int dy = pp / OW, ox = pp - dy*OW;
        pixbase[j] = 2*dy*RW + 2*ox*XS + 2*tq;
    }

    float4 acc[NTW];
    #pragma unroll
    for (int j = 0; j < NTW; j++) acc[j] = make_float4(0.f,0.f,0.f,0.f);

    const __half* swr = s_w + (m0 + gq)*APAD + 2*tq;
    #pragma unroll
    for (int s = 0; s < KS; s++) {
        uint32_t a0 = *(const uint32_t*)(swr + s*16);
        uint32_t a1 = *(const uint32_t*)(swr + s*16 + 8*APAD);
        uint32_t a2 = *(const uint32_t*)(swr + s*16 + 8);
        uint32_t a3 = *(const uint32_t*)(swr + s*16 + 8*APAD + 8);
        int off;
        if (C1) { off = s*RW; }
        else { int tap = s>>1, ch = s&1; int ky = tap/3, kx = tap - ky*3;
               off = ky*RW + kx*40 + ch*16; }
        #pragma unroll
        for (int j = 0; j < NTW; j++) {
            const __half* bp = s_in + pixbase[j] + off;
            mma16(acc[j], a0, a1, a2, a3,
                  *(const uint32_t*)bp, *(const uint32_t*)(bp + 8));
        }
    }

    const int oc = m0 + gq;
    const float b0v = __ldg(&bias[oc]);
    const float b8v = __ldg(&bias[oc+8]);
    __half* ob0 = (__half*)out_ + ((size_t)n0*OHW + oy0*OW)*32;

    #pragma unroll
    for (int j = 0; j < NTW; j++) {
        int tile = ng + 4*j;
        if (tile >= NT8) continue;
        int pc = tile*8 + tq*2;
        if (pc < NPIX) {
            ob0[pc*32 + oc]   = __float2half_rn(eluf(acc[j].x + b0v));
            ob0[pc*32 + oc+8] = __float2half_rn(eluf(acc[j].z + b8v));
        }
        if (pc+1 < NPIX) {
            ob0[(pc+1)*32 + oc]   = __float2half_rn(eluf(acc[j].y + b0v));
            ob0[(pc+1)*32 + oc+8] = __float2half_rn(eluf(acc[j].w + b8v));
        }
    }
}

// ---------------------------------------------------------------------------
// Fused conv3 + conv4 (unchanged from R5)
// ---------------------------------------------------------------------------
#define RW3  920
#define SIN3 (23*920)
#define RW4  520
#define SIN4 (13*520)
#define C34_SMEM ((SIN3 + SIN4 + 2*32*296) * 2)

__global__ void __launch_bounds__(256) conv34_f16(const __half* __restrict__ a2,
        const float* __restrict__ w3, const float* __restrict__ b3f,
        const float* __restrict__ w4, const float* __restrict__ b4f,
        __half* __restrict__ xf)
{
    extern __shared__ __half sh[];
    __half* s_in = sh;
    __half* s_c4 = sh + SIN3;
    __half* s_w3 = sh + SIN3 + SIN4;
    __half* s_w4 = s_w3 + 32*296;

    const int tid = threadIdx.x;
    const int n = blockIdx.x;

    for (int i = tid; i < (SIN3+SIN4)/8; i += 256) ((uint4*)s_in)[i] = make_uint4(0,0,0,0);

    for (int i = tid; i < 32*288; i += 256) {
        int oc = i/288, r = i - oc*288;
        int s = r>>4, c = r&15;
        int tap = s>>1, ch = s&1;
        int ky = tap/3, kx = tap - ky*3;
        int widx = ((oc*32 + ch*16 + c)*3+ky)*3+kx;
        s_w3[oc*296 + r] = __float2half_rn(w3[widx]);
        s_w4[oc*296 + r] = __float2half_rn(w4[widx]);
    }

    for (int i = tid; i < 21*21*4; i += 256) {
        int g = i & 3, q = i >> 2;
        int x = q % 21; int y = q / 21;
        uint4 v = *(const uint4*)(a2 + (((size_t)n*21 + y)*21 + x)*32 + g*8);
        *(uint4*)(s_in + (y+1)*RW3 + (x+1)*40 + g*8) = v;
    }
    __syncthreads();

    const int lane = tid & 31, warp = tid >> 5;
    const int m0 = (warp & 1)*16;
    const int ng = warp >> 1;
    const int gq = lane >> 2, tq = lane & 3;
    const int oc = m0 + gq;

    {
        int pixbase[4];
        #pragma unroll
        for (int j = 0; j < 4; j++) {
            int p = (ng + 4*j)*8 + gq;
            int pp = (p < 121) ? p : 0;
            int dy = pp / 11, ox = pp - dy*11;
            pixbase[j] = 2*dy*RW3 + 2*ox*40 + 2*tq;
        }
        float4 acc[4];
        #pragma unroll
        for (int j = 0; j < 4; j++) acc[j] = make_float4(0.f,0.f,0.f,0.f);

        const __half* swr = s_w3 + oc*296 + 2*tq;
        #pragma unroll
        for (int s = 0; s < 18; s++) {
            uint32_t a0 = *(const uint32_t*)(swr + s*16);
            uint32_t a1 = *(const uint32_t*)(swr + s*16 + 8*296);
            uint32_t a2r = *(const uint32_t*)(swr + s*16 + 8);
            uint32_t a3r = *(const uint32_t*)(swr + s*16 + 8*296 + 8);
            int tap = s>>1, ch = s&1; int ky = tap/3, kx = tap - ky*3;
            int off = ky*RW3 + kx*40 + ch*16;
            #pragma unroll
            for (int j = 0; j < 4; j++) {
                const __half* bp = s_in + pixbase[j] + off;
                mma16(acc[j], a0, a1, a2r, a3r,
                      *(const uint32_t*)bp, *(const uint32_t*)(bp + 8));
            }
        }
        const float b0v = __ldg(&b3f[oc]);
        const float b8v = __ldg(&b3f[oc+8]);
        #pragma unroll
        for (int j = 0; j < 4; j++) {
            int pc = (ng + 4*j)*8 + tq*2;
            #pragma unroll
            for (int u = 0; u < 2; u++) {
                int p = pc + u;
                if (p < 121) {
                    int y = p / 11, x = p - y*11;
                    __half* d = s_c4 + (y+1)*RW4 + (x+1)*40;
                    float v0 = (u == 0) ? acc[j].x : acc[j].y;
                    float v8 = (u == 0) ? acc[j].z : acc[j].w;
                    d[oc]   = __float2half_rn(eluf(v0 + b0v));
                    d[oc+8] = __float2half_rn(eluf(v8 + b8v));
                }
            }
        }
    }
    __syncthreads();

    {
        int pixbase[2];
        #pragma unroll
        for (int j = 0; j < 2; j++) {
            int tile = ng + 4*j;
            int p = tile*8 + gq;
            int pp = (p < 36) ? p : 0;
            int dy = pp / 6, ox = pp - dy*6;
            pixbase[j] = 2*dy*RW4 + 2*ox*40 + 2*tq;
        }
        float4 acc[2];
        acc[0] = make_float4(0.f,0.f,0.f,0.f); acc[1] = acc[0];

        const __half* swr = s_w4 + oc*296 + 2*tq;
        #pragma unroll
        for (int s = 0; s < 18; s++) {
            uint32_t a0 = *(const uint32_t*)(swr + s*16);
            uint32_t a1 = *(const uint32_t*)(swr + s*16 + 8*296);
            uint32_t a2r = *(const uint32_t*)(swr + s*16 + 8);
            uint32_t a3r = *(const uint32_t*)(swr + s*16 + 8*296 + 8);
            int tap = s>>1, ch = s&1; int ky = tap/3, kx = tap - ky*3;
            int off = ky*RW4 + kx*40 + ch*16;
            #pragma unroll
            for (int j = 0; j < 2; j++) {
                const __half* bp = s_c4 + pixbase[j] + off;
                mma16(acc[j], a0, a1, a2r, a3r,
                      *(const uint32_t*)bp, *(const uint32_t*)(bp + 8));
            }
        }
        const float b0v = __ldg(&b4f[oc]);
        const float b8v = __ldg(&b4f[oc+8]);
        __half* ob = xf + (size_t)n*1152;
        #pragma unroll
        for (int j = 0; j < 2; j++) {
            int tile = ng + 4*j;
            if (tile >= 5) continue;
            int pc = tile*8 + tq*2;
            if (pc < 36) {
                ob[oc*36 + pc]     = __float2half_rn(eluf(acc[j].x + b0v));
                ob[(oc+8)*36 + pc] = __float2half_rn(eluf(acc[j].z + b8v));
            }
            if (pc+1 < 36) {
                ob[oc*36 + pc+1]     = __float2half_rn(eluf(acc[j].y + b0v));
                ob[(oc+8)*36 + pc+1] = __float2half_rn(eluf(acc[j].w + b8v));
            }
        }
    }
}

// ---------------------------------------------------------------------------
// W_ih f32 -> f16 one-time conversion
// ---------------------------------------------------------------------------
__global__ void __launch_bounds__(256) wcvt(const float* __restrict__ W, __half* __restrict__ O) {
    int i = blockIdx.x * 256 + threadIdx.x;
    #pragma unroll
    for (int r = 0; r < 2; r++) {
        int idx = i + r * 110592;
        float4 v = *(const float4*)(W + idx*4);
        __half2 p0 = __floats2half2_rn(v.x, v.y);
        __half2 p1 = __floats2half2_rn(v.z, v.w);
        uint2 o; o.x = *(uint32_t*)&p0; o.y = *(uint32_t*)&p1;
        *(uint2*)(O + idx*4) = o;
    }
}

// ---------------------------------------------------------------------------
// gi[2048,768] = xf(f16) @ Wih(f16)^T + b_ih — clean 2-stage cp.async pipeline.
// ---------------------------------------------------------------------------
__global__ void __launch_bounds__(256) gemm_f16(const __half* __restrict__ A,
        const __half* __restrict__ B, const float* __restrict__ bias,
        float* __restrict__ C)
{
    constexpr int ST = 48;
    __shared__ __half As[2][64*ST], Bs[2][64*ST];
    const int bm = blockIdx.y*64, bn = blockIdx.x*64;
    const int tid = threadIdx.x, lane = tid&31, warp = tid>>5;
    const int wm = (warp&1)*32, wn = (warp>>1)*16;
    const int gq = lane>>2, tq = lane&3;
    const int ldr = tid>>2, ldc = (tid&3)*8;

    const __half* Ag = A + (size_t)(bm+ldr)*FEAT + ldc;
    const __half* Bg = B + (size_t)(bn+ldr)*FEAT + ldc;

    float4 acc[2][2];
    #pragma unroll
    for (int i = 0; i < 2; i++)
        #pragma unroll
        for (int j = 0; j < 2; j++) acc[i][j] = make_float4(0.f,0.f,0.f,0.f);

    cp16(&As[0][ldr*ST + ldc], Ag);
    cp16(&Bs[0][ldr*ST + ldc], Bg);
    asm volatile("cp.async.commit_group;");

    #pragma unroll 1
    for (int i = 0; i < 36; i++) {
        if (i + 1 < 36) {
            int st = (i+1)&1;
            cp16(&As[st][ldr*ST + ldc], Ag + (i+1)*32);
            cp16(&Bs[st][ldr*ST + ldc], Bg + (i+1)*32);
            asm volatile("cp.async.commit_group;");
            asm volatile("cp.async.wait_group 1;");
        } else {
            asm volatile("cp.async.wait_group 0;");
        }
        __syncthreads();
        const int cs = i&1;
        #pragma unroll
        for (int s = 0; s < 2; s++) {
            #pragma unroll
            for (int mi = 0; mi < 2; mi++) {
                const __half* ap = &As[cs][(wm + mi*16 + gq)*ST + s*16 + 2*tq];
                uint32_t a0 = *(const uint32_t*)ap;
                uint32_t a1 = *(const uint32_t*)(ap + 8*ST);
                uint32_t a2 = *(const uint32_t*)(ap + 8);
                uint32_t a3 = *(const uint32_t*)(ap + 8*ST + 8);
                #pragma unroll
                for (int ni = 0; ni < 2; ni++) {
                    const __half* bp = &Bs[cs][(wn + ni*8 + gq)*ST + s*16 + 2*tq];
                    mma16(acc[mi][ni], a0, a1, a2, a3,
                          *(const uint32_t*)bp, *(const uint32_t*)(bp + 8));
                }
            }
        }
        __syncthreads();
    }
    #pragma unroll
    for (int mi = 0; mi < 2; mi++) {
        #pragma unroll
        for (int ni = 0; ni < 2; ni++) {
            int row = bm + wm + mi*16 + gq;
            int col = bn + wn + ni*8 + tq*2;
            float bb0 = __ldg(&bias[col]), bb1 = __ldg(&bias[col+1]);
            C[(size_t)row*768 + col]       = acc[mi][ni].x + bb0;
            C[(size_t)row*768 + col + 1]   = acc[mi][ni].y + bb1;
            C[(size_t)(row+8)*768 + col]   = acc[mi][ni].z + bb0;
            C[(size_t)(row+8)*768 + col+1] = acc[mi][ni].w + bb1;
        }
    }
}

// ---------------------------------------------------------------------------
// Persistent GRU: 64 blocks x 256 threads, k-split x2.
// R5 atomic barrier (known-good) + XOR-swizzled s_h (conflict-free) + gi prefetch.
// ---------------------------------------------------------------------------
#define GRU_BLOCKS 64
#define GRU_THREADS 256

__device__ __forceinline__ void grid_barrier(unsigned target) {
    __threadfence();
    __syncthreads();
    if (threadIdx.x == 0) {
        unsigned v = atomicAdd(&g_bar_cnt, 1);
        if (v == GRU_BLOCKS - 1) {
            g_bar_cnt = 0;
            __threadfence();
            atomicAdd(&g_bar_phase, 1);
        } else {
            while ((int)(*(volatile unsigned*)&g_bar_phase - target) < 0) { __nanosleep(16); }
        }
        __threadfence();
    }
    __syncthreads();
}

__global__ void gru_kernel(const float* __restrict__ rnn_in, const float* __restrict__ mask,
                           const float* __restrict__ W_hh, const float* __restrict__ b_hh,
                           const float* __restrict__ gi_all, float* __restrict__ outs,
                           float* __restrict__ hfin) {
    __shared__ float s_w[12*256];
    __shared__ float s_h[32*256];
    __shared__ float s_p[3*256];

    const int tid = threadIdx.x;
    const int bx  = blockIdx.x;

    for (int i = tid; i < 12*64; i += GRU_THREADS) {
        int rl = i >> 6, kq = i & 63;
        int gate = rl >> 2, gj2 = rl & 3;
        float4 w = *(const float4*)&W_hh[(size_t)(gate*256 + bx*4 + gj2)*256 + kq*4];
        *(float4*)&s_w[rl*256 + kq*4] = w;
    }
    if (bx == 0) {
        for (int i = tid; i < BB*HID; i += GRU_THREADS) g_h[0][i] = rnn_in[i];
    }
    unsigned tgt = *(volatile unsigned*)&g_bar_phase;
    grid_barrier(++tgt);

    const int half = tid >> 7;
    const int r    = tid & 127;
    const int gj = r >> 5, b = r & 31;
    const int g = bx*4 + gj;
    const int c = b & 7;
    const float br = __ldg(&b_hh[g]);
    const float bz = __ldg(&b_hh[256 + g]);
    const float bn = __ldg(&b_hh[512 + g]);

    float4* s_h4 = (float4*)s_h;
    const float4* s_w4 = (const float4*)s_w;

    for (int t = 0; t < TT; t++) {
        float gir = 0.f, giz = 0.f, gin = 0.f;
        if (tid < 128) {
            const float* gi = gi_all + (size_t)(t*32 + b)*768;
            gir = __ldg(&gi[g]); giz = __ldg(&gi[256 + g]); gin = __ldg(&gi[512 + g]);
        }
        const float* hprev = g_h[t & 1];
        for (int i = tid; i < 32*64; i += GRU_THREADS) {
            int bb = i >> 6, kq = i & 63;
            float m = __ldg(&mask[t*32 + bb]);
            float4 hv = __ldcg((const float4*)&hprev[bb*256 + kq*4]);
            hv.x *= m; hv.y *= m; hv.z *= m; hv.w *= m;
            s_h4[bb*64 + (kq ^ (bb & 7))] = hv;   // XOR swizzle -> conflict-free reads
        }
        __syncthreads();

        float4 ar = make_float4(0.f,0.f,0.f,0.f), az = ar, an = ar;
        const float4* hrow = s_h4 + b*64;
        const float4* wr4 = s_w4 + (0 + gj)*64;
        const float4* wz4 = s_w4 + (4 + gj)*64;
        const float4* wn4 = s_w4 + (8 + gj)*64;
        #pragma unroll 8
        for (int kq = 0; kq < 32; kq++) {
            int kqg = half*32 + kq;
            float4 h = hrow[kqg ^ c];
            float4 wr = wr4[kqg], wz = wz4[kqg], wn = wn4[kqg];
            ar.x += h.x*wr.x; ar.y += h.y*wr.y; ar.z += h.z*wr.z; ar.w += h.w*wr.w;
            az.x += h.x*wz.x; az.y += h.y*wz.y; az.z += h.z*wz.z; az.w += h.w*wz.w;
            an.x += h.x*wn.x; an.y += h.y*wn.y; an.z += h.z*wn.z; an.w += h.w*wn.w;
        }
        s_p[0*256 + tid] = ar.x + ar.y + ar.z + ar.w;
        s_p[1*256 + tid] = az.x + az.y + az.z + az.w;
        s_p[2*256 + tid] = an.x + an.y + an.z + an.w;
        __syncthreads();
        if (tid < 128) {
            float ghr = s_p[0*256 + tid] + s_p[0*256 + tid + 128] + br;
            float ghz = s_p[1*256 + tid] + s_p[1*256 + tid + 128] + bz;
            float ghn = s_p[2*256 + tid] + s_p[2*256 + tid + 128] + bn;
            float rr = 1.f / (1.f + expf(-(gir + ghr)));
            float zz = 1.f / (1.f + expf(-(giz + ghz)));
            float nn = tanhf(gin + rr*ghn);
            float hold = s_h[b*256 + (((g>>2) ^ c)<<2) + (g&3)];
            float hn = (1.f - zz)*nn + zz*hold;
            g_h[(t + 1) & 1][b*256 + g] = hn;
            outs[(size_t)(t*32 + b)*256 + g] = hn;
            if (t == TT - 1) hfin[b*256 + g] = hn;
        }
        grid_barrier(++tgt);
    }
}

// ---------------------------------------------------------------------------
// Heads
// ---------------------------------------------------------------------------
__global__ void heads_kernel(const float* __restrict__ outs, const int* __restrict__ actions,
                             const float* __restrict__ Wc, const float* __restrict__ bc,
                             const float* __restrict__ Wa, const float* __restrict__ ba,
                             float* __restrict__ d_out) {
    int warp = (blockIdx.x * blockDim.x + threadIdx.x) >> 5;
    int lane = threadIdx.x & 31;
    if (warp >= NTB) return;
    const float* o = outs + (size_t)warp * 256;

    float acc[13];
    #pragma unroll
    for (int g = 0; g < 13; g++) acc[g] = 0.f;
    #pragma unroll
    for (int i = 0; i < 8; i++) {
        int k = lane + 32*i;
        float x = o[k];
        acc[0] += x * __ldg(&Wc[k]);
        #pragma unroll
        for (int g = 0; g < 12; g++) acc[1 + g] += x * __ldg(&Wa[g*256 + k]);
    }
    #pragma unroll
    for (int g = 0; g < 13; g++) {
        #pragma unroll
        for (int s = 16; s > 0; s >>= 1) acc[g] += __shfl_xor_sync(0xFFFFFFFFu, acc[g], s);
    }
    if (lane == 0) {
        float v = acc[0] + bc[0];
        float l[12];
        float m = -1e30f;
        #pragma unroll
        for (int g = 0; g < 12; g++) { l[g] = acc[1 + g] + ba[g]; m = fmaxf(m, l[g]); }
        float s = 0.f, sl = 0.f;
        #pragma unroll
        for (int g = 0; g < 12; g++) {
            float e = expf(l[g] - m);
            s += e; sl += e * l[g];
        }
        float logZ = m + logf(s);
        int a = actions[warp];
        d_out[warp]        = v;
        d_out[2048 + warp] = (float)a;
        d_out[4096 + warp] = l[a] - logZ;
        d_out[6144 + warp] = logZ - sl / s;
    }
}

// ---------------------------------------------------------------------------
// Host launcher
// ---------------------------------------------------------------------------
#define C1_SMEM ((13*344      + 32*56 ) * 2)
#define C2_SMEM ((15*(44*40)  + 32*296) * 2)

extern "C" void kernel_launch(void* const* d_in, const int* in_sizes, int n_in,
                              void* d_out, int out_size) {
    const float* inputs = (const float*)d_in[0];
    const float* rnn_in = (const float*)d_in[1];
    const float* mask   = (const float*)d_in[2];
    const int*   actions= (const int*)  d_in[3];
    const float* w1 = (const float*)d_in[4];  const float* b1 = (const float*)d_in[5];
    const float* w2 = (const float*)d_in[6];  const float* b2 = (const float*)d_in[7];
    const float* w3 = (const float*)d_in[8];  const float* b3 = (const float*)d_in[9];
    const float* w4 = (const float*)d_in[10]; const float* b4 = (const float*)d_in[11];
    const float* W_ih = (const float*)d_in[12];
    const float* W_hh = (const float*)d_in[13];
    const float* b_ih = (const float*)d_in[14];
    const float* b_hh = (const float*)d_in[15];
    const float* Wc = (const float*)d_in[16]; const float* bc = (const float*)d_in[17];
    const float* Wa = (const float*)d_in[18]; const float* ba = (const float*)d_in[19];
    float* out = (float*)d_out;

    __half *a1, *a2, *xf, *wih;
    float *gi, *outs;
    cudaGetSymbolAddress((void**)&a1, g_a1);
    cudaGetSymbolAddress((void**)&a2, g_a2);
    cudaGetSymbolAddress((void**)&xf, g_xf);
    cudaGetSymbolAddress((void**)&wih, g_wih);
    cudaGetSymbolAddress((void**)&gi, g_gi);
    cudaGetSymbolAddress((void**)&outs, g_outs);

    cudaFuncSetAttribute((conv_f16<4,84,42,6,0>),  cudaFuncAttributeMaxDynamicSharedMemorySize, C1_SMEM);
    cudaFuncSetAttribute((conv_f16<32,42,21,7,1>), cudaFuncAttributeMaxDynamicSharedMemorySize, C2_SMEM);
    cudaFuncSetAttribute(conv34_f16,               cudaFuncAttributeMaxDynamicSharedMemorySize, C34_SMEM);

    wcvt<<<432, 256>>>(W_ih, wih);
    conv_f16<4,84,42,6,0>  <<<dim3(NTB,7), 256, C1_SMEM>>>(inputs, w1, b1, a1);
    conv_f16<32,42,21,7,1> <<<dim3(NTB,3), 256, C2_SMEM>>>(a1, w2, b2, a2);
    conv34_f16             <<<NTB, 256, C34_SMEM>>>(a2, w3, b3, w4, b4, xf);

    gemm_f16<<<dim3(768/64, 2048/64), 256>>>(xf, wih, b_ih, gi);

    gru_kernel<<<GRU_BLOCKS, GRU_THREADS>>>(rnn_in, mask, W_hh, b_hh, gi, outs, out + 8192);

    heads_kernel<<<256, 256>>>(outs, actions, Wc, bc, Wa, ba, out);
}

// round 8
// speedup vs baseline: 1.2580x; 1.0360x over previous
#include <cuda_runtime.h>
#include <cuda_fp16.h>
#include <cstdint>

// ---------------------------------------------------------------------------
#define TT   64
#define BB   32
#define NTB  2048
#define HID  256
#define FEAT 1152

__device__ __half g_a1[2048u*32*42*42];   // NHWC f16
__device__ __half g_a2[2048u*32*21*21];   // NHWC f16
__device__ __half g_xf[2048u*1152];       // f16, reference feature order
__device__ __half g_wih[768u*1152];       // W_ih pre-converted to f16
__device__ __half g_wc[3*32*296];         // conv2/3/4 weights, k-major f16
__device__ float  g_gi[2048u*768];
__device__ float  g_outs[2048u*256];
__device__ float  g_h[2][BB*HID];
__device__ unsigned g_bar_cnt = 0;
__device__ unsigned g_bar_phase = 0;

// ---------------------------------------------------------------------------
__device__ __forceinline__ void mma16(float4& d, uint32_t a0, uint32_t a1,
                                      uint32_t a2, uint32_t a3,
                                      uint32_t b0, uint32_t b1) {
    asm volatile("mma.sync.aligned.m16n8k16.row.col.f32.f16.f16.f32 "
        "{%0,%1,%2,%3},{%4,%5,%6,%7},{%8,%9},{%0,%1,%2,%3};"
        : "+f"(d.x), "+f"(d.y), "+f"(d.z), "+f"(d.w)
        : "r"(a0), "r"(a1), "r"(a2), "r"(a3), "r"(b0), "r"(b1));
}
__device__ __forceinline__ float eluf(float x) { return x > 0.f ? x : expm1f(x); }

__device__ __forceinline__ void cp16(void* smem, const void* g) {
    uint32_t s = (uint32_t)__cvta_generic_to_shared(smem);
    asm volatile("cp.async.ca.shared.global [%0], [%1], 16;" :: "r"(s), "l"(g));
}

// ---------------------------------------------------------------------------
// One-time weight conversions
// ---------------------------------------------------------------------------
__global__ void __launch_bounds__(256) wcvt(const float* __restrict__ W, __half* __restrict__ O) {
    int i = blockIdx.x * 256 + threadIdx.x;
    #pragma unroll
    for (int r = 0; r < 2; r++) {
        int idx = i + r * 110592;
        float4 v = *(const float4*)(W + idx*4);
        __half2 p0 = __floats2half2_rn(v.x, v.y);
        __half2 p1 = __floats2half2_rn(v.z, v.w);
        uint2 o; o.x = *(uint32_t*)&p0; o.y = *(uint32_t*)&p1;
        *(uint2*)(O + idx*4) = o;
    }
}

// conv weights OIHW f32 -> [oc][s*16+c] f16 (s = tap*2+ch), stride 296
__global__ void __launch_bounds__(256) wcvtw(const float* __restrict__ w2,
        const float* __restrict__ w3, const float* __restrict__ w4) {
    const float* srcs[3] = {w2, w3, w4};
    for (int set = 0; set < 3; set++) {
        const float* W = srcs[set];
        for (int i = threadIdx.x + blockIdx.x*256; i < 32*296; i += gridDim.x*256) {
            int oc = i/296, r = i - oc*296;
            float f = 0.f;
            if (r < 288) {
                int s = r>>4, c = r&15, tap = s>>1, ch = s&1;
                int ky = tap/3, kx = tap - ky*3;
                f = W[((oc*32 + ch*16 + c)*3+ky)*3+kx];
            }
            g_wc[set*9472 + i] = __float2half_rn(f);
        }
    }
}

// ---------------------------------------------------------------------------
// fp16 implicit-GEMM conv3x3 stride2 pad1, OC=32, m16n8k16 (layers 1 & 2).
// IC=32 path uses pre-converted weights (pure uint4 copy).
// ---------------------------------------------------------------------------
template<int IC, int IH, int OH, int BAND, int INMODE>
__global__ void __launch_bounds__(256) conv_f16(const void* __restrict__ in_,
        const float* __restrict__ wgt, const __half* __restrict__ wgt16,
        const float* __restrict__ bias, void* __restrict__ out_)
{
    constexpr int OW = OH, IW = IH;
    constexpr bool C1 = (IC == 4);
    constexpr int XS = C1 ? 4 : 40;
    constexpr int RW = (IW+2)*XS;
    constexpr int ROWS = 2*BAND + 1;
    constexpr int SIN = ROWS*RW;
    constexpr int KS = C1 ? 3 : 18;
    constexpr int APAD = C1 ? 56 : 296;
    constexpr int NPIX = BAND*OW;
    constexpr int NT8 = (NPIX+7)/8;
    constexpr int NTW = (NT8+3)/4;
    constexpr int OHW = OH*OW;

    extern __shared__ __half sh[];
    __half* s_in = sh;
    __half* s_w  = sh + SIN;

    const int tid = threadIdx.x;
    const int n0 = blockIdx.x;
    const int oy0 = blockIdx.y * BAND;
    const int ybase = 2*oy0 - 1;

    for (int i = tid; i < SIN/8; i += 256) ((uint4*)s_in)[i] = make_uint4(0,0,0,0);

    if (C1) {
        for (int i = tid; i < 32*48; i += 256) {
            int oc = i/48, r = i - oc*48;
            int ky = r>>4, rr = r&15, kx = rr>>2, ic = rr&3;
            float v = (kx < 3) ? wgt[((oc*4+ic)*3+ky)*3+kx] : 0.f;
            s_w[oc*APAD + r] = __float2half_rn(v);
        }
    } else {
        for (int i = tid; i < 32*296/8; i += 256)
            ((uint4*)s_w)[i] = ((const uint4*)wgt16)[i];
    }

    const int y_lo = (ybase < 0) ? 0 : ybase;
    int y_hi = ybase + ROWS - 1; if (y_hi > IH-1) y_hi = IH-1;
    const int nrows = y_hi - y_lo + 1;

    if (INMODE == 0) {
        const float* inF = (const float*)in_;
        for (int i = tid; i < nrows*IW; i += 256) {
            int x = i % IW; int yy = i / IW; int y = y_lo + yy;
            const float* p = inF + (((size_t)n0*4)*IH + y)*IW + x;
            __half2 h01 = __floats2half2_rn(p[0], p[(size_t)IH*IW]);
            __half2 h23 = __floats2half2_rn(p[2*(size_t)IH*IW], p[3*(size_t)IH*IW]);
            __half* d = s_in + (y - ybase)*RW + (x+1)*4;
            *(__half2*)d = h01; *(__half2*)(d+2) = h23;
        }
    } else {
        const __half* inH = (const __half*)in_;
        for (int i = tid; i < nrows*IW*4; i += 256) {
            int g = i & 3, q = i >> 2;
            int x = q % IW; int yy = q / IW;
            int y = y_lo + yy;
            uint4 v = *(const uint4*)(inH + (((size_t)n0*IH + y)*IW + x)*32 + g*8);
            *(uint4*)(s_in + (y - ybase)*RW + (x+1)*40 + g*8) = v;
        }
    }
    __syncthreads();

    const int lane = tid & 31, warp = tid >> 5;
    const int m0 = (warp & 1)*16;
    const int ng = warp >> 1;
    const int gq = lane >> 2, tq = lane & 3;

    int pixbase[NTW];
    #pragma unroll
    for (int j = 0; j < NTW; j++) {
        int tile = ng + 4*j;
        int p = tile*8 + gq;
        int pp = (p < NPIX) ? p : 0;
        int dy = pp / OW, ox = pp - dy*OW;
        pixbase[j] = 2*dy*RW + 2*ox*XS + 2*tq;
    }

    float4 acc[NTW];
    #pragma unroll
    for (int j = 0; j < NTW; j++) acc[j] = make_float4(0.f,0.f,0.f,0.f);

    const __half* swr = s_w + (m0 + gq)*APAD + 2*tq;
    #pragma unroll
    for (int s = 0; s < KS; s++) {
        uint32_t a0 = *(const uint32_t*)(swr + s*16);
        uint32_t a1 = *(const uint32_t*)(swr + s*16 + 8*APAD);
        uint32_t a2 = *(const uint32_t*)(swr + s*16 + 8);
        uint32_t a3 = *(const uint32_t*)(swr + s*16 + 8*APAD + 8);
        int off;
        if (C1) { off = s*RW; }
        else { int tap = s>>1, ch = s&1; int ky = tap/3, kx = tap - ky*3;
               off = ky*RW + kx*40 + ch*16; }
        #pragma unroll
        for (int j = 0; j < NTW; j++) {
            const __half* bp = s_in + pixbase[j] + off;
            mma16(acc[j], a0, a1, a2, a3,
                  *(const uint32_t*)bp, *(const uint32_t*)(bp + 8));
        }
    }

    const int oc = m0 + gq;
    const float b0v = __ldg(&bias[oc]);
    const float b8v = __ldg(&bias[oc+8]);
    __half* ob0 = (__half*)out_ + ((size_t)n0*OHW + oy0*OW)*32;

    #pragma unroll
    for (int j = 0; j < NTW; j++) {
        int tile = ng + 4*j;
        if (tile >= NT8) continue;
        int pc = tile*8 + tq*2;
        if (pc < NPIX) {
            ob0[pc*32 + oc]   = __float2half_rn(eluf(acc[j].x + b0v));
            ob0[pc*32 + oc+8] = __float2half_rn(eluf(acc[j].z + b8v));
        }
        if (pc+1 < NPIX) {
            ob0[(pc+1)*32 + oc]   = __float2half_rn(eluf(acc[j].y + b0v));
            ob0[(pc+1)*32 + oc+8] = __float2half_rn(eluf(acc[j].w + b8v));
        }
    }
}

// ---------------------------------------------------------------------------
// Fused conv3 + conv4. conv3 done in TWO passes over a 13-row input buffer
// (output rows 0-5, then 6-10) -> smem 93.7KB -> 75.3KB -> 2 blocks/SM.
// Weights loaded pre-converted (pure uint4 copy).
// ---------------------------------------------------------------------------
#define RW3  920
#define SIN3 (13*920)     // 11960 halves
#define RW4  520
#define SIN4 (13*520)     // 6760 halves
#define C34_SMEM ((SIN3 + SIN4 + 2*32*296) * 2)   // 75,328 B

template<int NTWP>
__device__ __forceinline__ void conv3_pass(const __half* __restrict__ s_in,
        __half* __restrict__ s_c4, const __half* __restrict__ swr,
        int npix, int ng, int gq, int tq, int oc,
        float b0v, float b8v, int oybase)
{
    int pixbase[NTWP];
    #pragma unroll
    for (int j = 0; j < NTWP; j++) {
        int p = (ng + 4*j)*8 + gq;
        int pp = (p < npix) ? p : 0;
        int dy = pp / 11, ox = pp - dy*11;
        pixbase[j] = 2*dy*RW3 + 2*ox*40 + 2*tq;
    }
    float4 acc[NTWP];
    #pragma unroll
    for (int j = 0; j < NTWP; j++) acc[j] = make_float4(0.f,0.f,0.f,0.f);

    #pragma unroll
    for (int s = 0; s < 18; s++) {
        uint32_t a0 = *(const uint32_t*)(swr + s*16);
        uint32_t a1 = *(const uint32_t*)(swr + s*16 + 8*296);
        uint32_t a2r = *(const uint32_t*)(swr + s*16 + 8);
        uint32_t a3r = *(const uint32_t*)(swr + s*16 + 8*296 + 8);
        int tap = s>>1, ch = s&1; int ky = tap/3, kx = tap - ky*3;
        int off = ky*RW3 + kx*40 + ch*16;
        #pragma unroll
        for (int j = 0; j < NTWP; j++) {
            const __half* bp = s_in + pixbase[j] + off;
            mma16(acc[j], a0, a1, a2r, a3r,
                  *(const uint32_t*)bp, *(const uint32_t*)(bp + 8));
        }
    }
    #pragma unroll
    for (int j = 0; j < NTWP; j++) {
        int pc = (ng + 4*j)*8 + tq*2;
        #pragma unroll
        for (int u = 0; u < 2; u++) {
            int p = pc + u;
            if (p < npix) {
                int y = p / 11, x = p - y*11;
                __half* d = s_c4 + (oybase + y + 1)*RW4 + (x+1)*40;
                float v0 = (u == 0) ? acc[j].x : acc[j].y;
                float v8 = (u == 0) ? acc[j].z : acc[j].w;
                d[oc]   = __float2half_rn(eluf(v0 + b0v));
                d[oc+8] = __float2half_rn(eluf(v8 + b8v));
            }
        }
    }
}

__global__ void __launch_bounds__(256) conv34_f16(const __half* __restrict__ a2,
        const float* __restrict__ b3f, const float* __restrict__ b4f,
        __half* __restrict__ xf)
{
    extern __shared__ __half sh[];
    __half* s_in = sh;                    // 13 conv3 input rows
    __half* s_c4 = sh + SIN3;             // conv3 out / conv4 in, 13x13 slots
    __half* s_w3 = sh + SIN3 + SIN4;
    __half* s_w4 = s_w3 + 32*296;

    const int tid = threadIdx.x;
    const int n = blockIdx.x;

    // weights: pure copy of pre-converted sets 1 & 2 (contiguous in g_wc)
    for (int i = tid; i < 2*32*296/8; i += 256)
        ((uint4*)s_w3)[i] = ((const uint4*)(g_wc + 9472))[i];
    // zero conv4 input ring
    for (int i = tid; i < SIN4/8; i += 256) ((uint4*)s_c4)[i] = make_uint4(0,0,0,0);

    const int lane = tid & 31, warp = tid >> 5;
    const int m0 = (warp & 1)*16;
    const int ng = warp >> 1;
    const int gq = lane >> 2, tq = lane & 3;
    const int oc = m0 + gq;

    const float b30 = __ldg(&b3f[oc]);
    const float b38 = __ldg(&b3f[oc+8]);

    #pragma unroll
    for (int pass = 0; pass < 2; pass++) {
        // zero input buffer (halo)
        __syncthreads();
        for (int i = tid; i < SIN3/8; i += 256) ((uint4*)s_in)[i] = make_uint4(0,0,0,0);
        __syncthreads();
        const int ybase = pass ? 11 : -1;
        const int ylo = pass ? 11 : 0;
        const int yhi = pass ? 20 : 11;
        const int nrows = yhi - ylo + 1;
        for (int i = tid; i < nrows*21*4; i += 256) {
            int g = i & 3, q = i >> 2;
            int x = q % 21; int yy = q / 21;
            int y = ylo + yy;
            uint4 v = *(const uint4*)(a2 + (((size_t)n*21 + y)*21 + x)*32 + g*8);
            *(uint4*)(s_in + (y - ybase)*RW3 + (x+1)*40 + g*8) = v;
        }
        __syncthreads();
        const __half* swr3 = s_w3 + oc*296 + 2*tq;
        if (pass == 0)
            conv3_pass<3>(s_in, s_c4, swr3, 66, ng, gq, tq, oc, b30, b38, 0);
        else
            conv3_pass<2>(s_in, s_c4, swr3, 55, ng, gq, tq, oc, b30, b38, 6);
    }
    __syncthreads();

    // ---- conv4: NPIX=36, NT8=5, NTW=2 ----
    {
        int pixbase[2];
        #pragma unroll
        for (int j = 0; j < 2; j++) {
            int tile = ng + 4*j;
            int p = tile*8 + gq;
            int pp = (p < 36) ? p : 0;
            int dy = pp / 6, ox = pp - dy*6;
            pixbase[j] = 2*dy*RW4 + 2*ox*40 + 2*tq;
        }
        float4 acc[2];
        acc[0] = make_float4(0.f,0.f,0.f,0.f); acc[1] = acc[0];

        const __half* swr = s_w4 + oc*296 + 2*tq;
        #pragma unroll
        for (int s = 0; s < 18; s++) {
            uint32_t a0 = *(const uint32_t*)(swr + s*16);
            uint32_t a1 = *(const uint32_t*)(swr + s*16 + 8*296);
            uint32_t a2r = *(const uint32_t*)(swr + s*16 + 8);
            uint32_t a3r = *(const uint32_t*)(swr + s*16 + 8*296 + 8);
            int tap = s>>1, ch = s&1; int ky = tap/3, kx = tap - ky*3;
            int off = ky*RW4 + kx*40 + ch*16;
            #pragma unroll
            for (int j = 0; j < 2; j++) {
                const __half* bp = s_c4 + pixbase[j] + off;
                mma16(acc[j], a0, a1, a2r, a3r,
                      *(const uint32_t*)bp, *(const uint32_t*)(bp + 8));
            }
        }
        const float b0v = __ldg(&b4f[oc]);
        const float b8v = __ldg(&b4f[oc+8]);
        __half* ob = xf + (size_t)n*1152;
        #pragma unroll
        for (int j = 0; j < 2; j++) {
            int tile = ng + 4*j;
            if (tile >= 5) continue;
            int pc = tile*8 + tq*2;
            if (pc < 36) {
                ob[oc*36 + pc]     = __float2half_rn(eluf(acc[j].x + b0v));
                ob[(oc+8)*36 + pc] = __float2half_rn(eluf(acc[j].z + b8v));
            }
            if (pc+1 < 36) {
                ob[oc*36 + pc+1]     = __float2half_rn(eluf(acc[j].y + b0v));
                ob[(oc+8)*36 + pc+1] = __float2half_rn(eluf(acc[j].w + b8v));
            }
        }
    }
}

// ---------------------------------------------------------------------------
// gi[2048,768] = xf(f16) @ Wih(f16)^T + b_ih — 2-stage cp.async pipeline.
// ---------------------------------------------------------------------------
__global__ void __launch_bounds__(256) gemm_f16(const __half* __restrict__ A,
        const __half* __restrict__ B, const float* __restrict__ bias,
        float* __restrict__ C)
{
    constexpr int ST = 48;
    __shared__ __half As[2][64*ST], Bs[2][64*ST];
    const int bm = blockIdx.y*64, bn = blockIdx.x*64;
    const int tid = threadIdx.x, lane = tid&31, warp = tid>>5;
    const int wm = (warp&1)*32, wn = (warp>>1)*16;
    const int gq = lane>>2, tq = lane&3;
    const int ldr = tid>>2, ldc = (tid&3)*8;

    const __half* Ag = A + (size_t)(bm+ldr)*FEAT + ldc;
    const __half* Bg = B + (size_t)(bn+ldr)*FEAT + ldc;

    float4 acc[2][2];
    #pragma unroll
    for (int i = 0; i < 2; i++)
        #pragma unroll
        for (int j = 0; j < 2; j++) acc[i][j] = make_float4(0.f,0.f,0.f,0.f);

    cp16(&As[0][ldr*ST + ldc], Ag);
    cp16(&Bs[0][ldr*ST + ldc], Bg);
    asm volatile("cp.async.commit_group;");

    #pragma unroll 1
    for (int i = 0; i < 36; i++) {
        if (i + 1 < 36) {
            int st = (i+1)&1;
            cp16(&As[st][ldr*ST + ldc], Ag + (i+1)*32);
            cp16(&Bs[st][ldr*ST + ldc], Bg + (i+1)*32);
            asm volatile("cp.async.commit_group;");
            asm volatile("cp.async.wait_group 1;");
        } else {
            asm volatile("cp.async.wait_group 0;");
        }
        __syncthreads();
        const int cs = i&1;
        #pragma unroll
        for (int s = 0; s < 2; s++) {
            #pragma unroll
            for (int mi = 0; mi < 2; mi++) {
                const __half* ap = &As[cs][(wm + mi*16 + gq)*ST + s*16 + 2*tq];
                uint32_t a0 = *(const uint32_t*)ap;
                uint32_t a1 = *(const uint32_t*)(ap + 8*ST);
                uint32_t a2 = *(const uint32_t*)(ap + 8);
                uint32_t a3 = *(const uint32_t*)(ap + 8*ST + 8);
                #pragma unroll
                for (int ni = 0; ni < 2; ni++) {
                    const __half* bp = &Bs[cs][(wn + ni*8 + gq)*ST + s*16 + 2*tq];
                    mma16(acc[mi][ni], a0, a1, a2, a3,
                          *(const uint32_t*)bp, *(const uint32_t*)(bp + 8));
                }
            }
        }
        __syncthreads();
    }
    #pragma unroll
    for (int mi = 0; mi < 2; mi++) {
        #pragma unroll
        for (int ni = 0; ni < 2; ni++) {
            int row = bm + wm + mi*16 + gq;
            int col = bn + wn + ni*8 + tq*2;
            float bb0 = __ldg(&bias[col]), bb1 = __ldg(&bias[col+1]);
            C[(size_t)row*768 + col]       = acc[mi][ni].x + bb0;
            C[(size_t)row*768 + col + 1]   = acc[mi][ni].y + bb1;
            C[(size_t)(row+8)*768 + col]   = acc[mi][ni].z + bb0;
            C[(size_t)(row+8)*768 + col+1] = acc[mi][ni].w + bb1;
        }
    }
}

// ---------------------------------------------------------------------------
// Persistent GRU (unchanged from R7 — known good)
// ---------------------------------------------------------------------------
#define GRU_BLOCKS 64
#define GRU_THREADS 256

__device__ __forceinline__ void grid_barrier(unsigned target) {
    __threadfence();
    __syncthreads();
    if (threadIdx.x == 0) {
        unsigned v = atomicAdd(&g_bar_cnt, 1);
        if (v == GRU_BLOCKS - 1) {
            g_bar_cnt = 0;
            __threadfence();
            atomicAdd(&g_bar_phase, 1);
        } else {
            while ((int)(*(volatile unsigned*)&g_bar_phase - target) < 0) { __nanosleep(16); }
        }
        __threadfence();
    }
    __syncthreads();
}

__global__ void gru_kernel(const float* __restrict__ rnn_in, const float* __restrict__ mask,
                           const float* __restrict__ W_hh, const float* __restrict__ b_hh,
                           const float* __restrict__ gi_all, float* __restrict__ outs,
                           float* __restrict__ hfin) {
    __shared__ float s_w[12*256];
    __shared__ float s_h[32*256];
    __shared__ float s_p[3*256];

    const int tid = threadIdx.x;
    const int bx  = blockIdx.x;

    for (int i = tid; i < 12*64; i += GRU_THREADS) {
        int rl = i >> 6, kq = i & 63;
        int gate = rl >> 2, gj2 = rl & 3;
        float4 w = *(const float4*)&W_hh[(size_t)(gate*256 + bx*4 + gj2)*256 + kq*4];
        *(float4*)&s_w[rl*256 + kq*4] = w;
    }
    if (bx == 0) {
        for (int i = tid; i < BB*HID; i += GRU_THREADS) g_h[0][i] = rnn_in[i];
    }
    unsigned tgt = *(volatile unsigned*)&g_bar_phase;
    grid_barrier(++tgt);

    const int half = tid >> 7;
    const int r    = tid & 127;
    const int gj = r >> 5, b = r & 31;
    const int g = bx*4 + gj;
    const int c = b & 7;
    const float br = __ldg(&b_hh[g]);
    const float bz = __ldg(&b_hh[256 + g]);
    const float bn = __ldg(&b_hh[512 + g]);

    float4* s_h4 = (float4*)s_h;
    const float4* s_w4 = (const float4*)s_w;

    for (int t = 0; t < TT; t++) {
        float gir = 0.f, giz = 0.f, gin = 0.f;
        if (tid < 128) {
            const float* gi = gi_all + (size_t)(t*32 + b)*768;
            gir = __ldg(&gi[g]); giz = __ldg(&gi[256 + g]); gin = __ldg(&gi[512 + g]);
        }
        const float* hprev = g_h[t & 1];
        for (int i = tid; i < 32*64; i += GRU_THREADS) {
            int bb = i >> 6, kq = i & 63;
            float m = __ldg(&mask[t*32 + bb]);
            float4 hv = __ldcg((const float4*)&hprev[bb*256 + kq*4]);
            hv.x *= m; hv.y *= m; hv.z *= m; hv.w *= m;
            s_h4[bb*64 + (kq ^ (bb & 7))] = hv;
        }
        __syncthreads();

        float4 ar = make_float4(0.f,0.f,0.f,0.f), az = ar, an = ar;
        const float4* hrow = s_h4 + b*64;
        const float4* wr4 = s_w4 + (0 + gj)*64;
        const float4* wz4 = s_w4 + (4 + gj)*64;
        const float4* wn4 = s_w4 + (8 + gj)*64;
        #pragma unroll 8
        for (int kq = 0; kq < 32; kq++) {
            int kqg = half*32 + kq;
            float4 h = hrow[kqg ^ c];
            float4 wr = wr4[kqg], wz = wz4[kqg], wn = wn4[kqg];
            ar.x += h.x*wr.x; ar.y += h.y*wr.y; ar.z += h.z*wr.z; ar.w += h.w*wr.w;
            az.x += h.x*wz.x; az.y += h.y*wz.y; az.z += h.z*wz.z; az.w += h.w*wz.w;
            an.x += h.x*wn.x; an.y += h.y*wn.y; an.z += h.z*wn.z; an.w += h.w*wn.w;
        }
        s_p[0*256 + tid] = ar.x + ar.y + ar.z + ar.w;
        s_p[1*256 + tid] = az.x + az.y + az.z + az.w;
        s_p[2*256 + tid] = an.x + an.y + an.z + an.w;
        __syncthreads();
        if (tid < 128) {
            float ghr = s_p[0*256 + tid] + s_p[0*256 + tid + 128] + br;
            float ghz = s_p[1*256 + tid] + s_p[1*256 + tid + 128] + bz;
            float ghn = s_p[2*256 + tid] + s_p[2*256 + tid + 128] + bn;
            float rr = 1.f / (1.f + expf(-(gir + ghr)));
            float zz = 1.f / (1.f + expf(-(giz + ghz)));
            float nn = tanhf(gin + rr*ghn);
            float hold = s_h[b*256 + (((g>>2) ^ c)<<2) + (g&3)];
            float hn = (1.f - zz)*nn + zz*hold;
            g_h[(t + 1) & 1][b*256 + g] = hn;
            outs[(size_t)(t*32 + b)*256 + g] = hn;
            if (t == TT - 1) hfin[b*256 + g] = hn;
        }
        grid_barrier(++tgt);
    }
}

// ---------------------------------------------------------------------------
// Heads
// ---------------------------------------------------------------------------
__global__ void heads_kernel(const float* __restrict__ outs, const int* __restrict__ actions,
                             const float* __restrict__ Wc, const float* __restrict__ bc,
                             const float* __restrict__ Wa, const float* __restrict__ ba,
                             float* __restrict__ d_out) {
    int warp = (blockIdx.x * blockDim.x + threadIdx.x) >> 5;
    int lane = threadIdx.x & 31;
    if (warp >= NTB) return;
    const float* o = outs + (size_t)warp * 256;

    float acc[13];
    #pragma unroll
    for (int g = 0; g < 13; g++) acc[g] = 0.f;
    #pragma unroll
    for (int i = 0; i < 8; i++) {
        int k = lane + 32*i;
        float x = o[k];
        acc[0] += x * __ldg(&Wc[k]);
        #pragma unroll
        for (int g = 0; g < 12; g++) acc[1 + g] += x * __ldg(&Wa[g*256 + k]);
    }
    #pragma unroll
    for (int g = 0; g < 13; g++) {
        #pragma unroll
        for (int s = 16; s > 0; s >>= 1) acc[g] += __shfl_xor_sync(0xFFFFFFFFu, acc[g], s);
    }
    if (lane == 0) {
        float v = acc[0] + bc[0];
        float l[12];
        float m = -1e30f;
        #pragma unroll
        for (int g = 0; g < 12; g++) { l[g] = acc[1 + g] + ba[g]; m = fmaxf(m, l[g]); }
        float s = 0.f, sl = 0.f;
        #pragma unroll
        for (int g = 0; g < 12; g++) {
            float e = expf(l[g] - m);
            s += e; sl += e * l[g];
        }
        float logZ = m + logf(s);
        int a = actions[warp];
        d_out[warp]        = v;
        d_out[2048 + warp] = (float)a;
        d_out[4096 + warp] = l[a] - logZ;
        d_out[6144 + warp] = logZ - sl / s;
    }
}

// ---------------------------------------------------------------------------
// Host launcher
// ---------------------------------------------------------------------------
#define C1_SMEM ((13*344      + 32*56 ) * 2)
#define C2_SMEM ((15*(44*40)  + 32*296) * 2)

extern "C" void kernel_launch(void* const* d_in, const int* in_sizes, int n_in,
                              void* d_out, int out_size) {
    const float* inputs = (const float*)d_in[0];
    const float* rnn_in = (const float*)d_in[1];
    const float* mask   = (const float*)d_in[2];
    const int*   actions= (const int*)  d_in[3];
    const float* w1 = (const float*)d_in[4];  const float* b1 = (const float*)d_in[5];
    const float* w2 = (const float*)d_in[6];  const float* b2 = (const float*)d_in[7];
    const float* w3 = (const float*)d_in[8];  const float* b3 = (const float*)d_in[9];
    const float* w4 = (const float*)d_in[10]; const float* b4 = (const float*)d_in[11];
    const float* W_ih = (const float*)d_in[12];
    const float* W_hh = (const float*)d_in[13];
    const float* b_ih = (const float*)d_in[14];
    const float* b_hh = (const float*)d_in[15];
    const float* Wc = (const float*)d_in[16]; const float* bc = (const float*)d_in[17];
    const float* Wa = (const float*)d_in[18]; const float* ba = (const float*)d_in[19];
    float* out = (float*)d_out;

    __half *a1, *a2, *xf, *wih, *wc;
    float *gi, *outs;
    cudaGetSymbolAddress((void**)&a1, g_a1);
    cudaGetSymbolAddress((void**)&a2, g_a2);
    cudaGetSymbolAddress((void**)&xf, g_xf);
    cudaGetSymbolAddress((void**)&wih, g_wih);
    cudaGetSymbolAddress((void**)&wc, g_wc);
    cudaGetSymbolAddress((void**)&gi, g_gi);
    cudaGetSymbolAddress((void**)&outs, g_outs);

    cudaFuncSetAttribute((conv_f16<4,84,42,6,0>),  cudaFuncAttributeMaxDynamicSharedMemorySize, C1_SMEM);
    cudaFuncSetAttribute((conv_f16<32,42,21,7,1>), cudaFuncAttributeMaxDynamicSharedMemorySize, C2_SMEM);
    cudaFuncSetAttribute(conv34_f16,               cudaFuncAttributeMaxDynamicSharedMemorySize, C34_SMEM);

    wcvt<<<432, 256>>>(W_ih, wih);
    wcvtw<<<8, 256>>>(w2, w3, w4);
    conv_f16<4,84,42,6,0>  <<<dim3(NTB,7), 256, C1_SMEM>>>(inputs, w1, nullptr, b1, a1);
    conv_f16<32,42,21,7,1> <<<dim3(NTB,3), 256, C2_SMEM>>>(a1, nullptr, wc, b2, a2);
    conv34_f16             <<<NTB, 256, C34_SMEM>>>(a2, b3, b4, xf);

    gemm_f16<<<dim3(768/64, 2048/64), 256>>>(xf, wih, b_ih, gi);

    gru_kernel<<<GRU_BLOCKS, GRU_THREADS>>>(rnn_in, mask, W_hh, b_hh, gi, outs, out + 8192);

    heads_kernel<<<256, 256>>>(outs, actions, Wc, bc, Wa, ba, out);
}